// round 1
// baseline (speedup 1.0000x reference)
#include <cuda_runtime.h>
#include <cuda_bf16.h>

#define N_NODES 100000
#define N_EDGES 1600000
#define IN_F 128
#define OUT_F 48

// Scratch (no allocations allowed -> __device__ globals)
__device__ float g_h[(size_t)N_NODES * OUT_F];     // projected features
__device__ float g_ssrc[N_NODES];                  // h . w_src
__device__ float g_sdst[N_NODES];                  // h . w_dst
__device__ float g_e[N_EDGES];                     // leaky-relu logits
__device__ float g_ex[N_EDGES];                    // exp(e - m[dst])
__device__ float g_m[N_NODES];                     // segment max
__device__ float g_den[N_NODES];                   // segment sum of ex

// ---------------------------------------------------------------------------
// init: zero output, set m = -inf, den = 0
// ---------------------------------------------------------------------------
__global__ void k_init(float* __restrict__ out)
{
    int i = blockIdx.x * blockDim.x + threadIdx.x;
    if (i < N_NODES * OUT_F) out[i] = 0.0f;
    if (i < N_NODES) {
        g_m[i] = __int_as_float(0xFF800000);  // -inf
        g_den[i] = 0.0f;
    }
}

// ---------------------------------------------------------------------------
// GEMM: h = feat @ W^T + b ; also s_src = h.w_src, s_dst = h.w_dst
// 128 threads/block, each thread computes 2 nodes (register tile T=2),
// packed f32x2 FMAs, W pairs broadcast from SMEM.
// ---------------------------------------------------------------------------
__global__ void __launch_bounds__(128) k_gemm(
    const float* __restrict__ feat, const float* __restrict__ Ww,
    const float* __restrict__ Wb, const float* __restrict__ attnw)
{
    __shared__ unsigned long long sWp[IN_F][OUT_F / 2];  // [k][jj] = {W[2jj][k], W[2jj+1][k]}
    __shared__ float sb[OUT_F], sws[OUT_F], swd[OUT_F];

    int tid = threadIdx.x;
    for (int i = tid; i < IN_F * (OUT_F / 2); i += 128) {
        int k  = i / (OUT_F / 2);
        int jj = i % (OUT_F / 2);
        float lo = Ww[(2 * jj) * IN_F + k];
        float hi = Ww[(2 * jj + 1) * IN_F + k];
        unsigned long long p;
        asm("mov.b64 %0, {%1, %2};" : "=l"(p) : "f"(lo), "f"(hi));
        sWp[k][jj] = p;
    }
    if (tid < OUT_F) {
        sb[tid]  = Wb[tid];
        sws[tid] = attnw[tid];
        swd[tid] = attnw[OUT_F + tid];
    }
    __syncthreads();

    long n0 = (long)blockIdx.x * 256 + tid;
    long n1 = n0 + 128;
    bool v0 = n0 < N_NODES, v1 = n1 < N_NODES;
    const float4* r0 = (const float4*)(feat + (v0 ? n0 : 0) * IN_F);
    const float4* r1 = (const float4*)(feat + (v1 ? n1 : 0) * IN_F);

    unsigned long long a0[OUT_F / 2], a1[OUT_F / 2];
#pragma unroll
    for (int jj = 0; jj < OUT_F / 2; jj++) {
        unsigned long long p;
        asm("mov.b64 %0, {%1, %2};" : "=l"(p) : "f"(sb[2 * jj]), "f"(sb[2 * jj + 1]));
        a0[jj] = p;
        a1[jj] = p;
    }

#pragma unroll 2
    for (int k4 = 0; k4 < IN_F / 4; k4++) {
        float4 f0 = r0[k4];
        float4 f1 = r1[k4];
        float fs0[4] = {f0.x, f0.y, f0.z, f0.w};
        float fs1[4] = {f1.x, f1.y, f1.z, f1.w};
#pragma unroll
        for (int u = 0; u < 4; u++) {
            unsigned long long ff0, ff1;
            asm("mov.b64 %0, {%1, %1};" : "=l"(ff0) : "f"(fs0[u]));
            asm("mov.b64 %0, {%1, %1};" : "=l"(ff1) : "f"(fs1[u]));
            int k = 4 * k4 + u;
#pragma unroll
            for (int jj = 0; jj < OUT_F / 2; jj++) {
                unsigned long long w = sWp[k][jj];
                asm("fma.rn.f32x2 %0, %1, %2, %0;" : "+l"(a0[jj]) : "l"(ff0), "l"(w));
                asm("fma.rn.f32x2 %0, %1, %2, %0;" : "+l"(a1[jj]) : "l"(ff1), "l"(w));
            }
        }
    }

    if (v0) {
        float s1 = 0.0f, s2 = 0.0f;
        unsigned long long* hrow = (unsigned long long*)(g_h + (size_t)n0 * OUT_F);
#pragma unroll
        for (int jj = 0; jj < OUT_F / 2; jj++) {
            float lo, hi;
            asm("mov.b64 {%0, %1}, %2;" : "=f"(lo), "=f"(hi) : "l"(a0[jj]));
            s1 += lo * sws[2 * jj] + hi * sws[2 * jj + 1];
            s2 += lo * swd[2 * jj] + hi * swd[2 * jj + 1];
            hrow[jj] = a0[jj];
        }
        g_ssrc[n0] = s1;
        g_sdst[n0] = s2;
    }
    if (v1) {
        float s1 = 0.0f, s2 = 0.0f;
        unsigned long long* hrow = (unsigned long long*)(g_h + (size_t)n1 * OUT_F);
#pragma unroll
        for (int jj = 0; jj < OUT_F / 2; jj++) {
            float lo, hi;
            asm("mov.b64 {%0, %1}, %2;" : "=f"(lo), "=f"(hi) : "l"(a1[jj]));
            s1 += lo * sws[2 * jj] + hi * sws[2 * jj + 1];
            s2 += lo * swd[2 * jj] + hi * swd[2 * jj + 1];
            hrow[jj] = a1[jj];
        }
        g_ssrc[n1] = s1;
        g_sdst[n1] = s2;
    }
}

// ---------------------------------------------------------------------------
// edge1: e = leaky_relu(s_src[src]+s_dst[dst]+b), segment max into g_m
// ---------------------------------------------------------------------------
__global__ void k_edge1(const int* __restrict__ src, const int* __restrict__ dst,
                        const float* __restrict__ attnb)
{
    int e = blockIdx.x * blockDim.x + threadIdx.x;
    if (e >= N_EDGES) return;
    int s = src[e], d = dst[e];
    float v = g_ssrc[s] + g_sdst[d] + attnb[0];
    v = (v > 0.0f) ? v : 0.2f * v;
    g_e[e] = v;
    float* mp = &g_m[d];
    if (v >= 0.0f)
        atomicMax((int*)mp, __float_as_int(v));
    else
        atomicMin((unsigned int*)mp, __float_as_uint(v));
}

// ---------------------------------------------------------------------------
// edge2: ex = exp(e - m[dst]); den[dst] += ex
// ---------------------------------------------------------------------------
__global__ void k_edge2(const int* __restrict__ dst)
{
    int e = blockIdx.x * blockDim.x + threadIdx.x;
    if (e >= N_EDGES) return;
    int d = dst[e];
    float ex = __expf(g_e[e] - g_m[d]);
    g_ex[e] = ex;
    atomicAdd(&g_den[d], ex);
}

// ---------------------------------------------------------------------------
// edge3: out[dst] += h[src] * (ex / den[dst]) — 4 threads per edge,
// 16B vector reductions (red.global.add.v4.f32).
// ---------------------------------------------------------------------------
__device__ __forceinline__ void red_add_v4(float* addr, float a, float b, float c, float d)
{
    asm volatile("red.global.add.v4.f32 [%0], {%1, %2, %3, %4};"
                 :: "l"(addr), "f"(a), "f"(b), "f"(c), "f"(d) : "memory");
}

__global__ void k_edge3(const int* __restrict__ src, const int* __restrict__ dst,
                        float* __restrict__ out)
{
    int t = blockIdx.x * blockDim.x + threadIdx.x;
    int e = t >> 2;
    int part = t & 3;  // each part handles 12 of 48 outputs
    if (e >= N_EDGES) return;
    int s = src[e], d = dst[e];
    float alpha = g_ex[e] / g_den[d];
    const float4* hp = (const float4*)(g_h + (size_t)s * OUT_F) + part * 3;
    float* op = out + (size_t)d * OUT_F + part * 12;
#pragma unroll
    for (int i = 0; i < 3; i++) {
        float4 hv = hp[i];
        red_add_v4(op + i * 4, hv.x * alpha, hv.y * alpha, hv.z * alpha, hv.w * alpha);
    }
}

// ---------------------------------------------------------------------------
extern "C" void kernel_launch(void* const* d_in, const int* in_sizes, int n_in,
                              void* d_out, int out_size)
{
    const float* feat  = (const float*)d_in[0];
    const float* Ww    = (const float*)d_in[1];
    const float* Wb    = (const float*)d_in[2];
    const float* attnw = (const float*)d_in[3];
    const float* attnb = (const float*)d_in[4];
    const int*   src   = (const int*)d_in[5];
    const int*   dst   = (const int*)d_in[6];
    float* out = (float*)d_out;

    k_init<<<(N_NODES * OUT_F + 255) / 256, 256>>>(out);
    k_gemm<<<(N_NODES + 255) / 256, 128>>>(feat, Ww, Wb, attnw);
    k_edge1<<<(N_EDGES + 255) / 256, 256>>>(src, dst, attnb);
    k_edge2<<<(N_EDGES + 255) / 256, 256>>>(dst);
    k_edge3<<<((N_EDGES * 4) + 255) / 256, 256>>>(src, dst, out);
}

// round 2
// speedup vs baseline: 1.4447x; 1.4447x over previous
#include <cuda_runtime.h>
#include <cuda_bf16.h>

#define N_NODES 100000
#define N_EDGES 1600000
#define IN_F 128
#define OUT_F 48
#define NBLK_SCAN ((N_NODES + 1023) / 1024)   // 98

// Scratch (__device__ globals; no allocations allowed)
__device__ float g_h[(size_t)N_NODES * OUT_F];          // projected features
__device__ float g_ssrc[N_NODES];                       // h . w_src
__device__ float g_sdst[N_NODES];                       // h . w_dst
__device__ int   g_cnt[N_NODES];                        // degree (by dst)
__device__ int   g_off[N_NODES];                        // CSR offsets
__device__ int   g_cursor[N_NODES];                     // scatter cursors
__device__ int   g_bsum[128];                           // scan block sums
__device__ unsigned long long g_edge[N_EDGES];          // packed {src, ex}

// ---------------------------------------------------------------------------
__global__ void k_zero()
{
    int i = blockIdx.x * blockDim.x + threadIdx.x;
    if (i < N_NODES) g_cnt[i] = 0;
}

// ---------------------------------------------------------------------------
// GEMM: h = feat @ W^T + b ; also s_src = h.w_src, s_dst = h.w_dst
// ---------------------------------------------------------------------------
__global__ void __launch_bounds__(128) k_gemm(
    const float* __restrict__ feat, const float* __restrict__ Ww,
    const float* __restrict__ Wb, const float* __restrict__ attnw)
{
    __shared__ unsigned long long sWp[IN_F][OUT_F / 2];
    __shared__ float sb[OUT_F], sws[OUT_F], swd[OUT_F];

    int tid = threadIdx.x;
    for (int i = tid; i < IN_F * (OUT_F / 2); i += 128) {
        int k  = i / (OUT_F / 2);
        int jj = i % (OUT_F / 2);
        float lo = Ww[(2 * jj) * IN_F + k];
        float hi = Ww[(2 * jj + 1) * IN_F + k];
        unsigned long long p;
        asm("mov.b64 %0, {%1, %2};" : "=l"(p) : "f"(lo), "f"(hi));
        sWp[k][jj] = p;
    }
    if (tid < OUT_F) {
        sb[tid]  = Wb[tid];
        sws[tid] = attnw[tid];
        swd[tid] = attnw[OUT_F + tid];
    }
    __syncthreads();

    long n0 = (long)blockIdx.x * 256 + tid;
    long n1 = n0 + 128;
    bool v0 = n0 < N_NODES, v1 = n1 < N_NODES;
    const float4* r0 = (const float4*)(feat + (v0 ? n0 : 0) * IN_F);
    const float4* r1 = (const float4*)(feat + (v1 ? n1 : 0) * IN_F);

    unsigned long long a0[OUT_F / 2], a1[OUT_F / 2];
#pragma unroll
    for (int jj = 0; jj < OUT_F / 2; jj++) {
        unsigned long long p;
        asm("mov.b64 %0, {%1, %2};" : "=l"(p) : "f"(sb[2 * jj]), "f"(sb[2 * jj + 1]));
        a0[jj] = p;
        a1[jj] = p;
    }

#pragma unroll 2
    for (int k4 = 0; k4 < IN_F / 4; k4++) {
        float4 f0 = r0[k4];
        float4 f1 = r1[k4];
        float fs0[4] = {f0.x, f0.y, f0.z, f0.w};
        float fs1[4] = {f1.x, f1.y, f1.z, f1.w};
#pragma unroll
        for (int u = 0; u < 4; u++) {
            unsigned long long ff0, ff1;
            asm("mov.b64 %0, {%1, %1};" : "=l"(ff0) : "f"(fs0[u]));
            asm("mov.b64 %0, {%1, %1};" : "=l"(ff1) : "f"(fs1[u]));
            int k = 4 * k4 + u;
#pragma unroll
            for (int jj = 0; jj < OUT_F / 2; jj++) {
                unsigned long long w = sWp[k][jj];
                asm("fma.rn.f32x2 %0, %1, %2, %0;" : "+l"(a0[jj]) : "l"(ff0), "l"(w));
                asm("fma.rn.f32x2 %0, %1, %2, %0;" : "+l"(a1[jj]) : "l"(ff1), "l"(w));
            }
        }
    }

    if (v0) {
        float s1 = 0.0f, s2 = 0.0f;
        unsigned long long* hrow = (unsigned long long*)(g_h + (size_t)n0 * OUT_F);
#pragma unroll
        for (int jj = 0; jj < OUT_F / 2; jj++) {
            float lo, hi;
            asm("mov.b64 {%0, %1}, %2;" : "=f"(lo), "=f"(hi) : "l"(a0[jj]));
            s1 += lo * sws[2 * jj] + hi * sws[2 * jj + 1];
            s2 += lo * swd[2 * jj] + hi * swd[2 * jj + 1];
            hrow[jj] = a0[jj];
        }
        g_ssrc[n0] = s1;
        g_sdst[n0] = s2;
    }
    if (v1) {
        float s1 = 0.0f, s2 = 0.0f;
        unsigned long long* hrow = (unsigned long long*)(g_h + (size_t)n1 * OUT_F);
#pragma unroll
        for (int jj = 0; jj < OUT_F / 2; jj++) {
            float lo, hi;
            asm("mov.b64 {%0, %1}, %2;" : "=f"(lo), "=f"(hi) : "l"(a1[jj]));
            s1 += lo * sws[2 * jj] + hi * sws[2 * jj + 1];
            s2 += lo * swd[2 * jj] + hi * swd[2 * jj + 1];
            hrow[jj] = a1[jj];
        }
        g_ssrc[n1] = s1;
        g_sdst[n1] = s2;
    }
}

// ---------------------------------------------------------------------------
// Histogram of dst
// ---------------------------------------------------------------------------
__global__ void k_hist(const int* __restrict__ dst)
{
    int e = blockIdx.x * blockDim.x + threadIdx.x;
    if (e < N_EDGES) atomicAdd(&g_cnt[dst[e]], 1);
}

// ---------------------------------------------------------------------------
// Two-level exclusive scan of g_cnt -> g_off
// ---------------------------------------------------------------------------
__global__ void __launch_bounds__(1024) k_scan_block()
{
    __shared__ int wsum[32];
    int tid = threadIdx.x;
    int gid = blockIdx.x * 1024 + tid;
    int lane = tid & 31, wid = tid >> 5;
    int x = (gid < N_NODES) ? g_cnt[gid] : 0;
    int incl = x;
#pragma unroll
    for (int o = 1; o < 32; o <<= 1) {
        int y = __shfl_up_sync(0xFFFFFFFFu, incl, o);
        if (lane >= o) incl += y;
    }
    if (lane == 31) wsum[wid] = incl;
    __syncthreads();
    if (wid == 0) {
        int v = wsum[lane];
#pragma unroll
        for (int o = 1; o < 32; o <<= 1) {
            int y = __shfl_up_sync(0xFFFFFFFFu, v, o);
            if (lane >= o) v += y;
        }
        wsum[lane] = v;
    }
    __syncthreads();
    int wofs = (wid > 0) ? wsum[wid - 1] : 0;
    if (gid < N_NODES) g_off[gid] = wofs + incl - x;
    if (tid == 0) g_bsum[blockIdx.x] = wsum[31];
}

__global__ void __launch_bounds__(128) k_scan_sums()
{
    __shared__ int ws[4];
    int tid = threadIdx.x, lane = tid & 31, wid = tid >> 5;
    int x = (tid < NBLK_SCAN) ? g_bsum[tid] : 0;
    int incl = x;
#pragma unroll
    for (int o = 1; o < 32; o <<= 1) {
        int y = __shfl_up_sync(0xFFFFFFFFu, incl, o);
        if (lane >= o) incl += y;
    }
    if (lane == 31) ws[wid] = incl;
    __syncthreads();
    if (tid == 0) {
        int s = 0;
#pragma unroll
        for (int i = 0; i < 4; i++) { int t = ws[i]; ws[i] = s; s += t; }
    }
    __syncthreads();
    if (tid < NBLK_SCAN) g_bsum[tid] = ws[wid] + incl - x;
}

__global__ void __launch_bounds__(1024) k_scan_add()
{
    int gid = blockIdx.x * 1024 + threadIdx.x;
    if (gid < N_NODES) {
        int o = g_off[gid] + g_bsum[gid >> 10];
        g_off[gid] = o;
        g_cursor[gid] = o;
    }
}

// ---------------------------------------------------------------------------
// Scatter: compute ex = exp(leaky(s_src[s]+s_dst[d]+b)), place {src,ex}
// into dst-sorted position. No max-subtraction: logits are bounded, so
// exp(e)/sum(exp(e)) == exp(e-m)/sum(exp(e-m)) to fp32 rounding.
// ---------------------------------------------------------------------------
__global__ void k_scatter(const int* __restrict__ src, const int* __restrict__ dst,
                          const float* __restrict__ attnb)
{
    int e = blockIdx.x * blockDim.x + threadIdx.x;
    if (e >= N_EDGES) return;
    int s = src[e], d = dst[e];
    float v = g_ssrc[s] + g_sdst[d] + attnb[0];
    v = (v > 0.0f) ? v : 0.2f * v;
    float ex = __expf(v);
    int pos = atomicAdd(&g_cursor[d], 1);
    unsigned long long p =
        ((unsigned long long)(unsigned)s << 32) | (unsigned long long)__float_as_uint(ex);
    g_edge[pos] = p;
}

// ---------------------------------------------------------------------------
// Gather: 16 threads per node, 3 output floats each. Walk the node's edge
// segment, accumulate sum(h[src]*ex) and sum(ex), write acc/den. No atomics.
// ---------------------------------------------------------------------------
__global__ void __launch_bounds__(256) k_gather(float* __restrict__ out)
{
    int gt = blockIdx.x * blockDim.x + threadIdx.x;
    int n = gt >> 4;
    int t = gt & 15;
    if (n >= N_NODES) return;
    int start = g_off[n];
    int deg = g_cnt[n];
    int base = t * 3;
    float a0 = 0.0f, a1 = 0.0f, a2 = 0.0f, den = 0.0f;
    for (int k = 0; k < deg; k++) {
        unsigned long long p = g_edge[start + k];
        float ex = __uint_as_float((unsigned)p);
        int s = (int)(p >> 32);
        den += ex;
        const float* hp = g_h + (size_t)s * OUT_F + base;
        a0 = fmaf(hp[0], ex, a0);
        a1 = fmaf(hp[1], ex, a1);
        a2 = fmaf(hp[2], ex, a2);
    }
    float inv = (deg > 0) ? 1.0f / den : 0.0f;
    float* op = out + (size_t)n * OUT_F + base;
    op[0] = a0 * inv;
    op[1] = a1 * inv;
    op[2] = a2 * inv;
}

// ---------------------------------------------------------------------------
extern "C" void kernel_launch(void* const* d_in, const int* in_sizes, int n_in,
                              void* d_out, int out_size)
{
    const float* feat  = (const float*)d_in[0];
    const float* Ww    = (const float*)d_in[1];
    const float* Wb    = (const float*)d_in[2];
    const float* attnw = (const float*)d_in[3];
    const float* attnb = (const float*)d_in[4];
    const int*   src   = (const int*)d_in[5];
    const int*   dst   = (const int*)d_in[6];
    float* out = (float*)d_out;

    k_zero<<<(N_NODES + 255) / 256, 256>>>();
    k_gemm<<<(N_NODES + 255) / 256, 128>>>(feat, Ww, Wb, attnw);
    k_hist<<<(N_EDGES + 255) / 256, 256>>>(dst);
    k_scan_block<<<NBLK_SCAN, 1024>>>();
    k_scan_sums<<<1, 128>>>();
    k_scan_add<<<NBLK_SCAN, 1024>>>();
    k_scatter<<<(N_EDGES + 255) / 256, 256>>>(src, dst, attnb);
    k_gather<<<(N_NODES * 16 + 255) / 256, 256>>>(out);
}

// round 3
// speedup vs baseline: 1.6497x; 1.1419x over previous
#include <cuda_runtime.h>
#include <cuda_fp16.h>
#include <cuda_bf16.h>

#define N_NODES 100000
#define N_EDGES 1600000
#define IN_F 128
#define OUT_F 48
#define NBLK_SCAN ((N_NODES + 1023) / 1024)   // 98

// Scratch (__device__ globals; zero-initialized at load; no allocations allowed)
__device__ float  g_ssrc[N_NODES];                    // h . w_src
__device__ float  g_sdst[N_NODES];                    // h . w_dst
__device__ __half g_hh[(size_t)N_NODES * OUT_F];      // projected features (fp16)
__device__ int    g_cnt[N_NODES];                     // degree by dst (zero at entry!)
__device__ int    g_off[N_NODES];                     // CSR offsets
__device__ int    g_cursor[N_NODES];                  // scatter cursors
__device__ unsigned long long g_state[NBLK_SCAN];     // lookback state (zero at entry!)
__device__ unsigned long long g_edge[N_EDGES];        // packed {src, ex}

// ---------------------------------------------------------------------------
// GEMM + dst histogram.
// h = feat @ W^T + b (fp32 accum, stored fp16); s_src = h.w_src; s_dst = h.w_dst.
// Histogram atomics (no-return) issued first, drain under the FMA compute.
// ---------------------------------------------------------------------------
__global__ void __launch_bounds__(128) k_gemm(
    const float* __restrict__ feat, const float* __restrict__ Ww,
    const float* __restrict__ Wb, const float* __restrict__ attnw,
    const int* __restrict__ dst)
{
    // --- histogram of dst (grid-stride) ---
    {
        int gsz = gridDim.x * 128;
        for (int e = blockIdx.x * 128 + threadIdx.x; e < N_EDGES; e += gsz)
            atomicAdd(&g_cnt[dst[e]], 1);
    }

    __shared__ unsigned long long sWp[IN_F][OUT_F / 2];
    __shared__ float sb[OUT_F], sws[OUT_F], swd[OUT_F];

    int tid = threadIdx.x;
    for (int i = tid; i < IN_F * (OUT_F / 2); i += 128) {
        int k  = i / (OUT_F / 2);
        int jj = i % (OUT_F / 2);
        float lo = Ww[(2 * jj) * IN_F + k];
        float hi = Ww[(2 * jj + 1) * IN_F + k];
        unsigned long long p;
        asm("mov.b64 %0, {%1, %2};" : "=l"(p) : "f"(lo), "f"(hi));
        sWp[k][jj] = p;
    }
    if (tid < OUT_F) {
        sb[tid]  = Wb[tid];
        sws[tid] = attnw[tid];
        swd[tid] = attnw[OUT_F + tid];
    }
    __syncthreads();

    long n0 = (long)blockIdx.x * 256 + tid;
    long n1 = n0 + 128;
    bool v0 = n0 < N_NODES, v1 = n1 < N_NODES;
    const float4* r0 = (const float4*)(feat + (v0 ? n0 : 0) * IN_F);
    const float4* r1 = (const float4*)(feat + (v1 ? n1 : 0) * IN_F);

    unsigned long long a0[OUT_F / 2], a1[OUT_F / 2];
#pragma unroll
    for (int jj = 0; jj < OUT_F / 2; jj++) {
        unsigned long long p;
        asm("mov.b64 %0, {%1, %2};" : "=l"(p) : "f"(sb[2 * jj]), "f"(sb[2 * jj + 1]));
        a0[jj] = p;
        a1[jj] = p;
    }

#pragma unroll 2
    for (int k4 = 0; k4 < IN_F / 4; k4++) {
        float4 f0 = r0[k4];
        float4 f1 = r1[k4];
        float fs0[4] = {f0.x, f0.y, f0.z, f0.w};
        float fs1[4] = {f1.x, f1.y, f1.z, f1.w};
#pragma unroll
        for (int u = 0; u < 4; u++) {
            unsigned long long ff0, ff1;
            asm("mov.b64 %0, {%1, %1};" : "=l"(ff0) : "f"(fs0[u]));
            asm("mov.b64 %0, {%1, %1};" : "=l"(ff1) : "f"(fs1[u]));
            int k = 4 * k4 + u;
#pragma unroll
            for (int jj = 0; jj < OUT_F / 2; jj++) {
                unsigned long long w = sWp[k][jj];
                asm("fma.rn.f32x2 %0, %1, %2, %0;" : "+l"(a0[jj]) : "l"(ff0), "l"(w));
                asm("fma.rn.f32x2 %0, %1, %2, %0;" : "+l"(a1[jj]) : "l"(ff1), "l"(w));
            }
        }
    }

    if (v0) {
        float s1 = 0.0f, s2 = 0.0f;
        unsigned hh[OUT_F / 2];
#pragma unroll
        for (int jj = 0; jj < OUT_F / 2; jj++) {
            float lo, hi;
            asm("mov.b64 {%0, %1}, %2;" : "=f"(lo), "=f"(hi) : "l"(a0[jj]));
            s1 += lo * sws[2 * jj] + hi * sws[2 * jj + 1];
            s2 += lo * swd[2 * jj] + hi * swd[2 * jj + 1];
            __half2 h2 = __floats2half2_rn(lo, hi);
            hh[jj] = *(unsigned*)&h2;
        }
        uint4* hr = (uint4*)(g_hh + (size_t)n0 * OUT_F);
#pragma unroll
        for (int i = 0; i < 6; i++)
            hr[i] = make_uint4(hh[4 * i], hh[4 * i + 1], hh[4 * i + 2], hh[4 * i + 3]);
        g_ssrc[n0] = s1;
        g_sdst[n0] = s2;
    }
    if (v1) {
        float s1 = 0.0f, s2 = 0.0f;
        unsigned hh[OUT_F / 2];
#pragma unroll
        for (int jj = 0; jj < OUT_F / 2; jj++) {
            float lo, hi;
            asm("mov.b64 {%0, %1}, %2;" : "=f"(lo), "=f"(hi) : "l"(a1[jj]));
            s1 += lo * sws[2 * jj] + hi * sws[2 * jj + 1];
            s2 += lo * swd[2 * jj] + hi * swd[2 * jj + 1];
            __half2 h2 = __floats2half2_rn(lo, hi);
            hh[jj] = *(unsigned*)&h2;
        }
        uint4* hr = (uint4*)(g_hh + (size_t)n1 * OUT_F);
#pragma unroll
        for (int i = 0; i < 6; i++)
            hr[i] = make_uint4(hh[4 * i], hh[4 * i + 1], hh[4 * i + 2], hh[4 * i + 3]);
        g_ssrc[n1] = s1;
        g_sdst[n1] = s2;
    }
}

// ---------------------------------------------------------------------------
// Single-pass exclusive scan of g_cnt -> g_off/g_cursor (decoupled lookback).
// g_state flags: 0=invalid, 1=aggregate ready, 2=inclusive prefix ready.
// All 98 blocks co-resident on 148 SMs -> no deadlock.
// ---------------------------------------------------------------------------
__global__ void __launch_bounds__(1024) k_scan()
{
    __shared__ int wsum[32];
    __shared__ int s_prefix;
    int tid = threadIdx.x, bid = blockIdx.x;
    int gid = bid * 1024 + tid;
    int lane = tid & 31, wid = tid >> 5;
    int x = (gid < N_NODES) ? g_cnt[gid] : 0;
    int incl = x;
#pragma unroll
    for (int o = 1; o < 32; o <<= 1) {
        int y = __shfl_up_sync(0xFFFFFFFFu, incl, o);
        if (lane >= o) incl += y;
    }
    if (lane == 31) wsum[wid] = incl;
    __syncthreads();
    if (wid == 0) {
        int v = wsum[lane];
#pragma unroll
        for (int o = 1; o < 32; o <<= 1) {
            int y = __shfl_up_sync(0xFFFFFFFFu, v, o);
            if (lane >= o) v += y;
        }
        wsum[lane] = v;
    }
    __syncthreads();
    int wofs = (wid > 0) ? wsum[wid - 1] : 0;
    int total = wsum[31];

    if (tid == 0) {
        if (bid == 0) {
            atomicExch(&g_state[0], (2ULL << 62) | (unsigned)total);
            s_prefix = 0;
        } else {
            atomicExch(&g_state[bid], (1ULL << 62) | (unsigned)total);
            int run = 0;
            int j = bid - 1;
            while (true) {
                unsigned long long v = atomicAdd(&g_state[j], 0ULL);
                unsigned f = (unsigned)(v >> 62);
                if (f == 0) { __nanosleep(20); continue; }
                run += (int)(v & 0xFFFFFFFFULL);
                if (f == 2) break;
                j--;
            }
            atomicExch(&g_state[bid], (2ULL << 62) | (unsigned)(run + total));
            s_prefix = run;
        }
    }
    __syncthreads();
    if (gid < N_NODES) {
        int o = s_prefix + wofs + incl - x;
        g_off[gid] = o;
        g_cursor[gid] = o;
    }
}

// ---------------------------------------------------------------------------
// Scatter: ex = exp(leaky(s_src[s]+s_dst[d]+b)); place {src,ex} dst-sorted.
// No max-subtraction: logits bounded -> identical softmax to fp32 rounding.
// ---------------------------------------------------------------------------
__global__ void k_scatter(const int* __restrict__ src, const int* __restrict__ dst,
                          const float* __restrict__ attnb)
{
    int e = blockIdx.x * blockDim.x + threadIdx.x;
    if (e >= N_EDGES) return;
    int s = src[e], d = dst[e];
    float v = g_ssrc[s] + g_sdst[d] + attnb[0];
    v = (v > 0.0f) ? v : 0.2f * v;
    float ex = __expf(v);
    int pos = atomicAdd(&g_cursor[d], 1);
    unsigned long long p =
        ((unsigned long long)(unsigned)s << 32) | (unsigned long long)__float_as_uint(ex);
    g_edge[pos] = p;
}

// ---------------------------------------------------------------------------
// Gather: 8 threads/node, 6 outputs each (3x half2). Walk the node's edge
// segment, acc = sum(h[src]*ex), den = sum(ex); write acc/den. No atomics.
// Also restores the zero-invariants (g_cnt, g_state) for the next replay.
// ---------------------------------------------------------------------------
__global__ void __launch_bounds__(256) k_gather(float* __restrict__ out)
{
    int gt = blockIdx.x * blockDim.x + threadIdx.x;
    int n = gt >> 3;
    int t = gt & 7;
    if (n >= N_NODES) return;
    int start = g_off[n];
    int deg = g_cnt[n];

    const unsigned* H = (const unsigned*)g_hh;
    int hb = t * 3;  // u32 index within row (row = 24 u32)

    float a0 = 0.f, a1 = 0.f, a2 = 0.f, a3 = 0.f, a4 = 0.f, a5 = 0.f, den = 0.f;

    int k = 0;
    for (; k + 2 <= deg; k += 2) {
        unsigned long long p0 = g_edge[start + k];
        unsigned long long p1 = g_edge[start + k + 1];
        float ex0 = __uint_as_float((unsigned)p0);
        float ex1 = __uint_as_float((unsigned)p1);
        int s0 = (int)(p0 >> 32), s1 = (int)(p1 >> 32);
        const unsigned* h0 = H + s0 * 24 + hb;
        const unsigned* h1 = H + s1 * 24 + hb;
        unsigned w00 = h0[0], w01 = h0[1], w02 = h0[2];
        unsigned w10 = h1[0], w11 = h1[1], w12 = h1[2];
        den += ex0 + ex1;
        float2 f;
        f = __half22float2(*(__half2*)&w00); a0 = fmaf(f.x, ex0, a0); a1 = fmaf(f.y, ex0, a1);
        f = __half22float2(*(__half2*)&w01); a2 = fmaf(f.x, ex0, a2); a3 = fmaf(f.y, ex0, a3);
        f = __half22float2(*(__half2*)&w02); a4 = fmaf(f.x, ex0, a4); a5 = fmaf(f.y, ex0, a5);
        f = __half22float2(*(__half2*)&w10); a0 = fmaf(f.x, ex1, a0); a1 = fmaf(f.y, ex1, a1);
        f = __half22float2(*(__half2*)&w11); a2 = fmaf(f.x, ex1, a2); a3 = fmaf(f.y, ex1, a3);
        f = __half22float2(*(__half2*)&w12); a4 = fmaf(f.x, ex1, a4); a5 = fmaf(f.y, ex1, a5);
    }
    if (k < deg) {
        unsigned long long p0 = g_edge[start + k];
        float ex0 = __uint_as_float((unsigned)p0);
        int s0 = (int)(p0 >> 32);
        const unsigned* h0 = H + s0 * 24 + hb;
        unsigned w00 = h0[0], w01 = h0[1], w02 = h0[2];
        den += ex0;
        float2 f;
        f = __half22float2(*(__half2*)&w00); a0 = fmaf(f.x, ex0, a0); a1 = fmaf(f.y, ex0, a1);
        f = __half22float2(*(__half2*)&w01); a2 = fmaf(f.x, ex0, a2); a3 = fmaf(f.y, ex0, a3);
        f = __half22float2(*(__half2*)&w02); a4 = fmaf(f.x, ex0, a4); a5 = fmaf(f.y, ex0, a5);
    }

    float inv = (deg > 0) ? 1.0f / den : 0.0f;
    float2* op = (float2*)(out + (size_t)n * OUT_F + t * 6);
    op[0] = make_float2(a0 * inv, a1 * inv);
    op[1] = make_float2(a2 * inv, a3 * inv);
    op[2] = make_float2(a4 * inv, a5 * inv);

    // Restore zero-invariants for the next graph replay (deterministic:
    // identical work every call; __device__ globals start zeroed at load).
    if (t == 0) g_cnt[n] = 0;
    if (t == 1 && n < NBLK_SCAN) g_state[n] = 0ULL;
}

// ---------------------------------------------------------------------------
extern "C" void kernel_launch(void* const* d_in, const int* in_sizes, int n_in,
                              void* d_out, int out_size)
{
    const float* feat  = (const float*)d_in[0];
    const float* Ww    = (const float*)d_in[1];
    const float* Wb    = (const float*)d_in[2];
    const float* attnw = (const float*)d_in[3];
    const float* attnb = (const float*)d_in[4];
    const int*   src   = (const int*)d_in[5];
    const int*   dst   = (const int*)d_in[6];
    float* out = (float*)d_out;

    k_gemm<<<(N_NODES + 255) / 256, 128>>>(feat, Ww, Wb, attnw, dst);
    k_scan<<<NBLK_SCAN, 1024>>>();
    k_scatter<<<(N_EDGES + 255) / 256, 256>>>(src, dst, attnb);
    k_gather<<<(N_NODES * 8 + 255) / 256, 256>>>(out);
}